// round 10
// baseline (speedup 1.0000x reference)
#include <cuda_runtime.h>
#include <cuda_bf16.h>
#include <cstdint>

// Fan-model nonlinear mixing via mma.sync bf16 + cp.async.bulk stores.
//   out[b,x] = L + (L^2 - Q)/2,  L = sum_p E[b,p] a[p,x],  Q = sum_p E^2 a^2
// bf16 hi/lo split, K stacked (al*el dropped).
// R10 = R9 with loop-invariant address math hoisted, 4-deep store ring.

#define NPIX (512 * 512)
#define NP   12
#define NB   224
#define NOCT (NB / 8)            // 28

// smem layout
#define SM_TBLE 0                // 28*32*16 = 14336
#define SM_TBLF 14336            // 14336
#define SM_BUF  28672            // 4 ring buffers
#define BUF_PITCH_W 132          // floats per band row (128 + 4 pad)
#define BUF_BYTES   (8 * BUF_PITCH_W * 4)   // 4224 per buffer
#define SM_TOTAL (SM_BUF + 4 * BUF_BYTES)   // 45568

// fragment-order B tables: [mat][octet][lane] = uint4
__device__ __align__(16) uint4 g_tbl[2][NOCT][32];

static __device__ __forceinline__ uint32_t pk(float lo, float hi) {
    uint32_t r;
    asm("cvt.rn.bf16x2.f32 %0, %1, %2;" : "=r"(r) : "f"(hi), "f"(lo));
    return r;
}

__global__ void prep_kernel(const float* __restrict__ E) {
    int idx = blockIdx.x * blockDim.x + threadIdx.x;
    if (idx >= NOCT * 32) return;
    int o = idx >> 5, t = idx & 31;
    int g = t >> 2, i = t & 3;
    int band = o * 8 + g;

    float eh[16], el[16], fh[16], fl[16];
#pragma unroll
    for (int p = 0; p < 16; p++) {
        float e = (p < NP) ? E[band * NP + p] : 0.0f;
        float f = e * e;
        float ehp = __bfloat162float(__float2bfloat16(e));
        float fhp = __bfloat162float(__float2bfloat16(f));
        eh[p] = e;  el[p] = e - ehp;
        fh[p] = f;  fl[p] = f - fhp;
    }
    uint4 ve, vf;
    ve.x = pk(eh[2 * i], eh[2 * i + 1]);
    ve.y = pk(eh[8 + 2 * i], eh[8 + 2 * i + 1]);
    ve.z = pk(el[2 * i], el[2 * i + 1]);
    ve.w = pk(el[8 + 2 * i], el[8 + 2 * i + 1]);
    vf.x = pk(fh[2 * i], fh[2 * i + 1]);
    vf.y = pk(fh[8 + 2 * i], fh[8 + 2 * i + 1]);
    vf.z = pk(fl[2 * i], fl[2 * i + 1]);
    vf.w = pk(fl[8 + 2 * i], fl[8 + 2 * i + 1]);
    g_tbl[0][o][t] = ve;
    g_tbl[1][o][t] = vf;
}

#define MMA(c0,c1,c2,c3,a0,a1,a2,a3,b0,b1) \
    asm volatile("mma.sync.aligned.m16n8k16.row.col.f32.bf16.bf16.f32 " \
        "{%0,%1,%2,%3}, {%4,%5,%6,%7}, {%8,%9}, {%0,%1,%2,%3};" \
        : "+f"(c0), "+f"(c1), "+f"(c2), "+f"(c3) \
        : "r"(a0), "r"(a1), "r"(a2), "r"(a3), "r"(b0), "r"(b1))

__global__ __launch_bounds__(256) void fm_mma_kernel(
    const float* __restrict__ A, float* __restrict__ out)
{
    extern __shared__ char sm[];
    {
        const uint4* src = &g_tbl[0][0][0];
        uint4* dst = reinterpret_cast<uint4*>(sm);
        for (int j = threadIdx.x; j < 2 * NOCT * 32; j += 256) dst[j] = src[j];
    }

    uint32_t sbase;
    asm("{ .reg .u64 t; cvta.to.shared.u64 t, %1; cvt.u32.u64 %0, t; }"
        : "=r"(sbase) : "l"(sm));

    const int tid = threadIdx.x;
    const int t = tid & 31;
    const int w = tid >> 5;
    const int g = t >> 2;
    const int i = t & 3;
    const int px0 = blockIdx.x * 128;
    const int pxA = px0 + w * 16 + g;
    const int pxB = pxA + 8;

    // ---- A fragments (built once) ----
    const int p0 = 2 * i, p1 = 2 * i + 1;
    const int p2 = 2 * i + 8, p3 = 2 * i + 9;
    float vA0 = __ldg(A + (size_t)p0 * NPIX + pxA);
    float vA1 = __ldg(A + (size_t)p1 * NPIX + pxA);
    float vB0 = __ldg(A + (size_t)p0 * NPIX + pxB);
    float vB1 = __ldg(A + (size_t)p1 * NPIX + pxB);
    float vA2 = (i < 2) ? __ldg(A + (size_t)p2 * NPIX + pxA) : 0.0f;
    float vA3 = (i < 2) ? __ldg(A + (size_t)p3 * NPIX + pxA) : 0.0f;
    float vB2 = (i < 2) ? __ldg(A + (size_t)p2 * NPIX + pxB) : 0.0f;
    float vB3 = (i < 2) ? __ldg(A + (size_t)p3 * NPIX + pxB) : 0.0f;

#define SPLIT(v, h, l) float h = __bfloat162float(__float2bfloat16(v)); float l = (v) - h;
    SPLIT(vA0, hA0, lA0) SPLIT(vA1, hA1, lA1) SPLIT(vA2, hA2, lA2) SPLIT(vA3, hA3, lA3)
    SPLIT(vB0, hB0, lB0) SPLIT(vB1, hB1, lB1) SPLIT(vB2, hB2, lB2) SPLIT(vB3, hB3, lB3)
    float sA0 = vA0 * vA0, sA1 = vA1 * vA1, sA2 = vA2 * vA2, sA3 = vA3 * vA3;
    float sB0 = vB0 * vB0, sB1 = vB1 * vB1, sB2 = vB2 * vB2, sB3 = vB3 * vB3;
    SPLIT(sA0, hsA0, lsA0) SPLIT(sA1, hsA1, lsA1) SPLIT(sA2, hsA2, lsA2) SPLIT(sA3, hsA3, lsA3)
    SPLIT(sB0, hsB0, lsB0) SPLIT(sB1, hsB1, lsB1) SPLIT(sB2, hsB2, lsB2) SPLIT(sB3, hsB3, lsB3)

    uint32_t aH0 = pk(vA0, vA1), aH1 = pk(vB0, vB1), aH2 = pk(vA2, vA3), aH3 = pk(vB2, vB3);
    uint32_t aL0 = pk(lA0, lA1), aL1 = pk(lB0, lB1), aL2 = pk(lA2, lA3), aL3 = pk(lB2, lB3);
    uint32_t sH0 = pk(sA0, sA1), sH1 = pk(sB0, sB1), sH2 = pk(sA2, sA3), sH3 = pk(sB2, sB3);
    uint32_t sL0 = pk(lsA0, lsA1), sL1 = pk(lsB0, lsB1), sL2 = pk(lsA2, lsA3), sL3 = pk(lsB2, lsB3);

    // ---- loop-invariant addresses (hoisted) ----
    const int pxl = w * 16 + g;
    const uint32_t st0 = sbase + SM_BUF + ((2 * i) * BUF_PITCH_W + pxl) * 4;
    const uint32_t st1 = st0 + BUF_PITCH_W * 4;        // band 2i+1
    const uint32_t frE = sbase + SM_TBLE + t * 16;
    const uint32_t frF = sbase + SM_TBLF + t * 16;
    // bulk source/dst for tid<8 (band lane = tid)
    const uint32_t bsrc0 = sbase + SM_BUF + (uint32_t)tid * (BUF_PITCH_W * 4);
    const float* gdst = out + (size_t)tid * NPIX + px0;   // +8*NPIX per octet

    __syncthreads();   // tables visible

#pragma unroll 1
    for (int o = 0; o < NOCT; o++) {
        uint4 ue, uf;
        asm("ld.shared.v4.b32 {%0,%1,%2,%3}, [%4];"
            : "=r"(ue.x), "=r"(ue.y), "=r"(ue.z), "=r"(ue.w)
            : "r"(frE + (uint32_t)o * 512));
        asm("ld.shared.v4.b32 {%0,%1,%2,%3}, [%4];"
            : "=r"(uf.x), "=r"(uf.y), "=r"(uf.z), "=r"(uf.w)
            : "r"(frF + (uint32_t)o * 512));

        float cl0 = 0.f, cl1 = 0.f, cl2 = 0.f, cl3 = 0.f;
        float cq0 = 0.f, cq1 = 0.f, cq2 = 0.f, cq3 = 0.f;
        MMA(cl0, cl1, cl2, cl3, aH0, aH1, aH2, aH3, ue.x, ue.y);  // ah*eh
        MMA(cl0, cl1, cl2, cl3, aL0, aL1, aL2, aL3, ue.x, ue.y);  // al*eh
        MMA(cl0, cl1, cl2, cl3, aH0, aH1, aH2, aH3, ue.z, ue.w);  // ah*el
        MMA(cq0, cq1, cq2, cq3, sH0, sH1, sH2, sH3, uf.x, uf.y);  // sh*fh
        MMA(cq0, cq1, cq2, cq3, sL0, sL1, sL2, sL3, uf.x, uf.y);  // sl*fh
        MMA(cq0, cq1, cq2, cq3, sH0, sH1, sH2, sH3, uf.z, uf.w);  // sh*fl

        float r0 = fmaf(0.5f, fmaf(cl0, cl0, -cq0), cl0);
        float r1 = fmaf(0.5f, fmaf(cl1, cl1, -cq1), cl1);
        float r2 = fmaf(0.5f, fmaf(cl2, cl2, -cq2), cl2);
        float r3 = fmaf(0.5f, fmaf(cl3, cl3, -cq3), cl3);

        const uint32_t boff = (uint32_t)(o & 3) * BUF_BYTES;

        // ring slot free? (its reader was bulk group o-4)
        if (o >= 4 && tid < 8)
            asm volatile("cp.async.bulk.wait_group.read 3;" ::: "memory");
        __syncthreads();

        asm volatile("st.shared.f32 [%0], %1;" :: "r"(st0 + boff), "f"(r0));
        asm volatile("st.shared.f32 [%0], %1;" :: "r"(st1 + boff), "f"(r1));
        asm volatile("st.shared.f32 [%0], %1;" :: "r"(st0 + boff + 32), "f"(r2));
        asm volatile("st.shared.f32 [%0], %1;" :: "r"(st1 + boff + 32), "f"(r3));
        asm volatile("fence.proxy.async.shared::cta;" ::: "memory");
        __syncthreads();

        if (tid < 8) {
            asm volatile(
                "cp.async.bulk.global.shared::cta.bulk_group [%0], [%1], 512;"
                :: "l"(gdst), "r"(bsrc0 + boff) : "memory");
            asm volatile("cp.async.bulk.commit_group;" ::: "memory");
        }
        gdst += 8 * (size_t)NPIX;
    }
    if (tid < 8)
        asm volatile("cp.async.bulk.wait_group 0;" ::: "memory");
}

extern "C" void kernel_launch(void* const* d_in, const int* in_sizes, int n_in,
                              void* d_out, int out_size)
{
    const float* E = (const float*)d_in[0];
    const float* A = (const float*)d_in[1];
    if (in_sizes[0] > in_sizes[1]) {
        E = (const float*)d_in[1];
        A = (const float*)d_in[0];
    }
    float* out = (float*)d_out;

    cudaFuncSetAttribute(fm_mma_kernel,
                         cudaFuncAttributeMaxDynamicSharedMemorySize, SM_TOTAL);

    prep_kernel<<<7, 128>>>(E);
    fm_mma_kernel<<<NPIX / 128, 256, SM_TOTAL>>>(A, out);
}

// round 11
// speedup vs baseline: 1.3469x; 1.3469x over previous
#include <cuda_runtime.h>
#include <cuda_bf16.h>
#include <cstdint>

// Fan-model nonlinear mixing via mma.sync bf16 (R8 lineage):
//   out[b,x] = L + (L^2 - Q)/2,  L = sum_p E[b,p] a[p,x],  Q = sum_p E^2 a^2
// bf16 hi/lo split, K stacked (al*el dropped).
// R11: 64 px per warp (4 m16n8k16 M-tiles). Output transposed through a
// WARP-PRIVATE smem tile (conflict-free pitch 68) -> fully coalesced
// STG.128 (4 full lines per instruction). No CTA barriers in the loop.

#define NPIX (512 * 512)
#define NP   12
#define NB   224
#define NOCT (NB / 8)            // 28

#define PITCH_W 68                        // floats per band row (64 + 4)
#define WBUF_BYTES (8 * PITCH_W * 4)      // 2176 per warp
#define SM_TBLF_OFF 14336
#define SM_BUF 28672                      // tables: 2*28*32*16
#define SM_TOTAL (SM_BUF + 4 * WBUF_BYTES)  // 37376

// fragment-order B tables: [mat][octet][lane] = uint4
__device__ __align__(16) uint4 g_tbl[2][NOCT][32];

static __device__ __forceinline__ uint32_t pk(float lo, float hi) {
    uint32_t r;
    asm("cvt.rn.bf16x2.f32 %0, %1, %2;" : "=r"(r) : "f"(hi), "f"(lo));
    return r;
}

__global__ void prep_kernel(const float* __restrict__ E) {
    int idx = blockIdx.x * blockDim.x + threadIdx.x;
    if (idx >= NOCT * 32) return;
    int o = idx >> 5, t = idx & 31;
    int g = t >> 2, i = t & 3;
    int band = o * 8 + g;

    float eh[16], el[16], fh[16], fl[16];
#pragma unroll
    for (int p = 0; p < 16; p++) {
        float e = (p < NP) ? E[band * NP + p] : 0.0f;
        float f = e * e;
        float ehp = __bfloat162float(__float2bfloat16(e));
        float fhp = __bfloat162float(__float2bfloat16(f));
        eh[p] = e;  el[p] = e - ehp;
        fh[p] = f;  fl[p] = f - fhp;
    }
    uint4 ve, vf;
    ve.x = pk(eh[2 * i], eh[2 * i + 1]);
    ve.y = pk(eh[8 + 2 * i], eh[8 + 2 * i + 1]);
    ve.z = pk(el[2 * i], el[2 * i + 1]);
    ve.w = pk(el[8 + 2 * i], el[8 + 2 * i + 1]);
    vf.x = pk(fh[2 * i], fh[2 * i + 1]);
    vf.y = pk(fh[8 + 2 * i], fh[8 + 2 * i + 1]);
    vf.z = pk(fl[2 * i], fl[2 * i + 1]);
    vf.w = pk(fl[8 + 2 * i], fl[8 + 2 * i + 1]);
    g_tbl[0][o][t] = ve;
    g_tbl[1][o][t] = vf;
}

#define MMA(c0,c1,c2,c3,a0,a1,a2,a3,b0,b1) \
    asm volatile("mma.sync.aligned.m16n8k16.row.col.f32.bf16.bf16.f32 " \
        "{%0,%1,%2,%3}, {%4,%5,%6,%7}, {%8,%9}, {%0,%1,%2,%3};" \
        : "+f"(c0), "+f"(c1), "+f"(c2), "+f"(c3) \
        : "r"(a0), "r"(a1), "r"(a2), "r"(a3), "r"(b0), "r"(b1))

__global__ __launch_bounds__(128) void fm_mma_kernel(
    const float* __restrict__ A, float* __restrict__ out)
{
    extern __shared__ char sm[];
    {   // copy both fragment tables (1792 uint4)
        const uint4* src = &g_tbl[0][0][0];
        uint4* dst = reinterpret_cast<uint4*>(sm);
        for (int j = threadIdx.x; j < 2 * NOCT * 32; j += 128) dst[j] = src[j];
    }
    uint32_t sbase;
    asm("{ .reg .u64 t; cvta.to.shared.u64 t, %1; cvt.u32.u64 %0, t; }"
        : "=r"(sbase) : "l"(sm));

    const int tid = threadIdx.x;
    const int t = tid & 31;
    const int w = tid >> 5;          // warp 0..3
    const int g = t >> 2;            // 0..7
    const int i = t & 3;             // 0..3
    const int pxw = blockIdx.x * 256 + w * 64;   // warp's first pixel

    // ---- A fragments for 4 M-tiles (built once) ----
    uint32_t aH[4][4], aL[4][4], sH[4][4], sL[4][4];
    const int p0 = 2 * i, p1 = 2 * i + 1;
    const int p2 = 2 * i + 8, p3 = 2 * i + 9;
#pragma unroll
    for (int m = 0; m < 4; m++) {
        const int pxA = pxw + 16 * m + g;
        const int pxB = pxA + 8;
        float vA0 = __ldg(A + (size_t)p0 * NPIX + pxA);
        float vA1 = __ldg(A + (size_t)p1 * NPIX + pxA);
        float vB0 = __ldg(A + (size_t)p0 * NPIX + pxB);
        float vB1 = __ldg(A + (size_t)p1 * NPIX + pxB);
        float vA2 = (i < 2) ? __ldg(A + (size_t)p2 * NPIX + pxA) : 0.0f;
        float vA3 = (i < 2) ? __ldg(A + (size_t)p3 * NPIX + pxA) : 0.0f;
        float vB2 = (i < 2) ? __ldg(A + (size_t)p2 * NPIX + pxB) : 0.0f;
        float vB3 = (i < 2) ? __ldg(A + (size_t)p3 * NPIX + pxB) : 0.0f;

#define SPLIT(v, h, l) float h = __bfloat162float(__float2bfloat16(v)); float l = (v) - h;
        SPLIT(vA0, hA0, lA0) SPLIT(vA1, hA1, lA1) SPLIT(vA2, hA2, lA2) SPLIT(vA3, hA3, lA3)
        SPLIT(vB0, hB0, lB0) SPLIT(vB1, hB1, lB1) SPLIT(vB2, hB2, lB2) SPLIT(vB3, hB3, lB3)
        float q0 = vA0 * vA0, q1 = vA1 * vA1, q2 = vA2 * vA2, q3 = vA3 * vA3;
        float u0 = vB0 * vB0, u1 = vB1 * vB1, u2 = vB2 * vB2, u3 = vB3 * vB3;
        SPLIT(q0, hq0, lq0) SPLIT(q1, hq1, lq1) SPLIT(q2, hq2, lq2) SPLIT(q3, hq3, lq3)
        SPLIT(u0, hu0, lu0) SPLIT(u1, hu1, lu1) SPLIT(u2, hu2, lu2) SPLIT(u3, hu3, lu3)

        aH[m][0] = pk(vA0, vA1); aH[m][1] = pk(vB0, vB1);
        aH[m][2] = pk(vA2, vA3); aH[m][3] = pk(vB2, vB3);
        aL[m][0] = pk(lA0, lA1); aL[m][1] = pk(lB0, lB1);
        aL[m][2] = pk(lA2, lA3); aL[m][3] = pk(lB2, lB3);
        sH[m][0] = pk(q0, q1);   sH[m][1] = pk(u0, u1);
        sH[m][2] = pk(q2, q3);   sH[m][3] = pk(u2, u3);
        sL[m][0] = pk(lq0, lq1); sL[m][1] = pk(lu0, lu1);
        sL[m][2] = pk(lq2, lq3); sL[m][3] = pk(lu2, lu3);
    }

    // ---- loop-invariant addresses ----
    const uint32_t frE = sbase + t * 16;
    const uint32_t frF = sbase + SM_TBLF_OFF + t * 16;
    const uint32_t wbuf = sbase + SM_BUF + (uint32_t)w * WBUF_BYTES;
    // STS: band row 2i, pixel column g (conflict-free, pitch 68)
    const uint32_t st_b = wbuf + ((uint32_t)(2 * i) * PITCH_W + g) * 4;
    // LDS-back: lane t reads band row (t>>4), 4 px at (t&15)*4
    const uint32_t ld_b = wbuf + (uint32_t)(t >> 4) * (PITCH_W * 4) + (t & 15) * 16;
    // STG: band (t>>4) + 2 per round, pixel pxw + (t&15)*4
    float* gp = out + (size_t)(t >> 4) * NPIX + pxw + (t & 15) * 4;

    __syncthreads();   // tables visible

#pragma unroll 1
    for (int o = 0; o < NOCT; o++) {
        uint4 ue, uf;
        asm("ld.shared.v4.b32 {%0,%1,%2,%3}, [%4];"
            : "=r"(ue.x), "=r"(ue.y), "=r"(ue.z), "=r"(ue.w)
            : "r"(frE + (uint32_t)o * 512));
        asm("ld.shared.v4.b32 {%0,%1,%2,%3}, [%4];"
            : "=r"(uf.x), "=r"(uf.y), "=r"(uf.z), "=r"(uf.w)
            : "r"(frF + (uint32_t)o * 512));

#pragma unroll
        for (int m = 0; m < 4; m++) {
            float cl0 = 0.f, cl1 = 0.f, cl2 = 0.f, cl3 = 0.f;
            float cq0 = 0.f, cq1 = 0.f, cq2 = 0.f, cq3 = 0.f;
            MMA(cl0, cl1, cl2, cl3, aH[m][0], aH[m][1], aH[m][2], aH[m][3], ue.x, ue.y);
            MMA(cl0, cl1, cl2, cl3, aL[m][0], aL[m][1], aL[m][2], aL[m][3], ue.x, ue.y);
            MMA(cl0, cl1, cl2, cl3, aH[m][0], aH[m][1], aH[m][2], aH[m][3], ue.z, ue.w);
            MMA(cq0, cq1, cq2, cq3, sH[m][0], sH[m][1], sH[m][2], sH[m][3], uf.x, uf.y);
            MMA(cq0, cq1, cq2, cq3, sL[m][0], sL[m][1], sL[m][2], sL[m][3], uf.x, uf.y);
            MMA(cq0, cq1, cq2, cq3, sH[m][0], sH[m][1], sH[m][2], sH[m][3], uf.z, uf.w);

            float r0 = fmaf(0.5f, fmaf(cl0, cl0, -cq0), cl0);  // (band 2i,   px g)
            float r1 = fmaf(0.5f, fmaf(cl1, cl1, -cq1), cl1);  // (band 2i+1, px g)
            float r2 = fmaf(0.5f, fmaf(cl2, cl2, -cq2), cl2);  // (band 2i,   px g+8)
            float r3 = fmaf(0.5f, fmaf(cl3, cl3, -cq3), cl3);  // (band 2i+1, px g+8)

            const uint32_t sb = st_b + m * 64;   // +16 px per tile
            asm volatile("st.shared.f32 [%0], %1;" :: "r"(sb), "f"(r0));
            asm volatile("st.shared.f32 [%0], %1;" :: "r"(sb + PITCH_W * 4), "f"(r1));
            asm volatile("st.shared.f32 [%0], %1;" :: "r"(sb + 32), "f"(r2));
            asm volatile("st.shared.f32 [%0], %1;" :: "r"(sb + PITCH_W * 4 + 32), "f"(r3));
        }
        __syncwarp();

#pragma unroll
        for (int r = 0; r < 4; r++) {
            uint4 q;
            asm("ld.shared.v4.b32 {%0,%1,%2,%3}, [%4];"
                : "=r"(q.x), "=r"(q.y), "=r"(q.z), "=r"(q.w)
                : "r"(ld_b + (uint32_t)r * (2 * PITCH_W * 4)));
            asm volatile("st.global.cs.v4.b32 [%0], {%1,%2,%3,%4};"
                         :: "l"(gp), "r"(q.x), "r"(q.y), "r"(q.z), "r"(q.w)
                         : "memory");
            gp += 2 * (size_t)NPIX;
        }
        __syncwarp();   // buffer reuse guard
    }
}

extern "C" void kernel_launch(void* const* d_in, const int* in_sizes, int n_in,
                              void* d_out, int out_size)
{
    const float* E = (const float*)d_in[0];
    const float* A = (const float*)d_in[1];
    if (in_sizes[0] > in_sizes[1]) {
        E = (const float*)d_in[1];
        A = (const float*)d_in[0];
    }
    float* out = (float*)d_out;

    cudaFuncSetAttribute(fm_mma_kernel,
                         cudaFuncAttributeMaxDynamicSharedMemorySize, SM_TOTAL);

    prep_kernel<<<7, 128>>>(E);
    fm_mma_kernel<<<NPIX / 256, 128, SM_TOTAL>>>(A, out);  // 1024 blocks
}